// round 9
// baseline (speedup 1.0000x reference)
#include <cuda_runtime.h>
#include <cstdint>

#define NA    57600     // 64*100*9 anchors
#define NLOC  6400      // 64*100
#define FW    100
#define PRE   6000
#define POST  300
#define NW    94        // ceil(6000/64) u64 words
#define CAP   8192
#define NBIN  65536
#define NCO   1024
#define FULL  0xFFFFFFFFu
#define QD    8         // candidates per pipeline group

typedef unsigned long long u64;

// Base anchors (ratios 0.5,1,2 x scales 8,16,32), numpy banker's rounding baked in.
__constant__ float c_base[36] = {
  -84.f,  -40.f,  99.f,  55.f,
 -176.f,  -88.f, 191.f, 103.f,
 -360.f, -184.f, 375.f, 199.f,
  -56.f,  -56.f,  71.f,  71.f,
 -120.f, -120.f, 135.f, 135.f,
 -248.f, -248.f, 263.f, 263.f,
  -36.f,  -80.f,  51.f,  95.f,
  -80.f, -168.f,  95.f, 183.f,
 -168.f, -344.f, 183.f, 359.f
};

// NOTE: g_hist/g_coarse/g_rank/g_cnt must be ZERO on entry to each run.
// They start zero (static init) and are re-zeroed by k_mask each run.
__device__ float4   g_boxes[NA];
__device__ unsigned g_keys[NA];
__device__ unsigned g_hist[NBIN];
__device__ unsigned g_coarse[NCO];
__device__ int      g_cnt;
__device__ unsigned g_B;
__device__ u64      g_cand[CAP];
__device__ int      g_rank[CAP];
__device__ float4   g_top[PRE];
__device__ u64      g_mask[(size_t)PRE * NW];   // triangular: words < i/64 of row i NOT written

// ---------------------------------------------------------------- decode + fine/coarse histograms
__global__ void k_decode(const float* __restrict__ cls,
                         const float* __restrict__ bbox,
                         const int*   __restrict__ ih,
                         const int*   __restrict__ iw) {
    int t = blockIdx.x * blockDim.x + threadIdx.x;
    if (t >= NA) return;
    int a = t / NLOC, loc = t % NLOC;       // coalesced channel reads
    int y = loc / FW, x = loc % FW;
    int ai = loc * 9 + a;                   // reference anchor index

    float s0 = cls[(2 * a)     * NLOC + loc];
    float s1 = cls[(2 * a + 1) * NLOC + loc];
    float m  = fmaxf(s0, s1);
    float e0 = expf(s0 - m), e1 = expf(s1 - m);
    float score = e1 / (e0 + e1);

    float dx = bbox[(4 * a + 0) * NLOC + loc];
    float dy = bbox[(4 * a + 1) * NLOC + loc];
    float dw = bbox[(4 * a + 2) * NLOC + loc];
    float dh = bbox[(4 * a + 3) * NLOC + loc];

    float sx = (float)(x * 16), sy = (float)(y * 16);
    float ax1 = sx + c_base[a * 4 + 0];
    float ay1 = sy + c_base[a * 4 + 1];
    float ax2 = sx + c_base[a * 4 + 2];
    float ay2 = sy + c_base[a * 4 + 3];

    float w  = ax2 - ax1 + 1.0f;
    float h  = ay2 - ay1 + 1.0f;
    float cx = ax1 + 0.5f * w;
    float cy = ay1 + 0.5f * h;

    float pcx = dx * w + cx;
    float pcy = dy * h + cy;
    float pw  = expf(dw) * w;
    float ph  = expf(dh) * h;

    float W = (float)(iw[0] - 1);
    float H = (float)(ih[0] - 1);
    float x1 = fminf(fmaxf(pcx - 0.5f * pw, 0.f), W);
    float y1 = fminf(fmaxf(pcy - 0.5f * ph, 0.f), H);
    float x2 = fminf(fmaxf(pcx + 0.5f * pw, 0.f), W);
    float y2 = fminf(fmaxf(pcy + 0.5f * ph, 0.f), H);

    bool valid = (x2 - x1 + 1.f >= 16.f) && (y2 - y1 + 1.f >= 16.f);
    float s = valid ? score : -1e30f;

    unsigned u = __float_as_uint(s);
    unsigned key = (u & 0x80000000u) ? ~u : (u | 0x80000000u);

    g_keys[t]   = key;
    g_boxes[ai] = make_float4(x1, y1, x2, y2);
    atomicAdd(&g_hist[key >> 16], 1u);
    atomicAdd(&g_coarse[key >> 22], 1u);
}

// ---------------------------------------------------------------- threshold bin via coarse hist (1 block)
__global__ void k_thresh() {
    __shared__ unsigned warpsum[32];
    __shared__ unsigned warpsuf[32];
    int t = threadIdx.x;            // 1024 threads, one per coarse bucket
    int lane = t & 31, warp = t >> 5;

    unsigned c = g_coarse[t];

    unsigned suf = c;
    #pragma unroll
    for (int off = 1; off < 32; off <<= 1) {
        unsigned v = __shfl_down_sync(FULL, suf, off);
        if (lane + off < 32) suf += v;
    }
    if (lane == 0) warpsum[warp] = suf;
    __syncthreads();
    if (warp == 0) {
        unsigned ws = warpsum[lane];
        unsigned s2 = ws;
        #pragma unroll
        for (int off = 1; off < 32; off <<= 1) {
            unsigned v = __shfl_down_sync(FULL, s2, off);
            if (lane + off < 32) s2 += v;
        }
        warpsuf[lane] = s2 - ws;
    }
    __syncthreads();

    unsigned suffInc = suf + warpsuf[warp];
    unsigned above   = suffInc - c;
    if (above < PRE && suffInc >= PRE) {
        unsigned run = above;
        int base = t * 64;          // coarse bucket t = fine bins [t*64, t*64+64)
        for (int b = 63; b >= 0; b--) {
            run += g_hist[base + b];
            if (run >= PRE) { g_B = (unsigned)(base + b); break; }
        }
    }
}

// ---------------------------------------------------------------- compact candidates (bin >= threshold bin)
__global__ void k_compact() {
    int t = blockIdx.x * blockDim.x + threadIdx.x;
    if (t >= NA) return;
    unsigned key = g_keys[t];
    if ((key >> 16) >= g_B) {
        int p = atomicAdd(&g_cnt, 1);
        if (p < CAP) {
            int a = t / NLOC, loc = t % NLOC;
            unsigned ai = (unsigned)(loc * 9 + a);
            g_cand[p] = ((u64)key << 32) | (~ai);
        }
    }
}

// ---------------------------------------------------------------- 2D-parallel exact rank (partial counts via atomics)
__global__ void k_rank2d() {
    __shared__ u64 tile[256];
    int cnt = g_cnt; if (cnt > CAP) cnt = CAP;
    if (blockIdx.x * 256 >= cnt || blockIdx.y * 256 >= cnt) return;  // uniform early exit
    int j = blockIdx.y * 256 + threadIdx.x;
    tile[threadIdx.x] = (j < cnt) ? g_cand[j] : 0ULL;   // zeros never beat valid keys
    __syncthreads();
    int p = blockIdx.x * 256 + threadIdx.x;
    if (p >= cnt) return;
    u64 v = g_cand[p];
    int r = 0;
    #pragma unroll 8
    for (int q = 0; q < 256; q++) r += (tile[q] > v);
    if (r) atomicAdd(&g_rank[p], r);
}

// ---------------------------------------------------------------- scatter boxes to rank order
__global__ void k_scatter() {
    int cnt = g_cnt; if (cnt > CAP) cnt = CAP;
    int p = blockIdx.x * 256 + threadIdx.x;
    if (p >= cnt) return;
    int r = g_rank[p];
    if (r < PRE) {
        u64 v = g_cand[p];
        unsigned idx = ~(unsigned)v;
        g_top[r] = g_boxes[idx];
    }
}

// ---------------------------------------------------------------- IoU bitmask (upper-triangular) + state re-zero
__global__ void k_mask() {
    __shared__ float4 sb[64];
    int cb = blockIdx.x, rb = blockIdx.y, t = threadIdx.x;

    // housekeeping for the NEXT run: zero hist/coarse/rank/cnt (safe: all
    // consumers of these ran in earlier kernels of THIS run)
    {
        int bid = blockIdx.y * gridDim.x + blockIdx.x;
        int gt  = bid * 64 + t;
        if (gt < NBIN)                       g_hist[gt] = 0u;
        else if (gt < NBIN + NCO)            g_coarse[gt - NBIN] = 0u;
        else if (gt < NBIN + NCO + CAP)      g_rank[gt - NBIN - NCO] = 0;
        else if (gt == NBIN + NCO + CAP)     g_cnt = 0;
    }

    if (cb < rb) return;           // sub-diagonal: never written, never read
    int i = rb * 64 + t;
    int j0 = cb * 64;
    int jg = j0 + t;
    sb[t] = (jg < PRE) ? g_top[jg] : make_float4(0.f, 0.f, 0.f, 0.f);
    __syncthreads();
    if (i >= PRE) return;
    float4 bi = g_top[i];
    float ai = (bi.z - bi.x) * (bi.w - bi.y);
    u64 bits = 0ULL;
    #pragma unroll 4
    for (int b = 0; b < 64; b++) {
        int j = j0 + b;
        float4 bj = sb[b];
        float aj = (bj.z - bj.x) * (bj.w - bj.y);
        float lx = fmaxf(bi.x, bj.x), ly = fmaxf(bi.y, bj.y);
        float rx = fminf(bi.z, bj.z), ry = fminf(bi.w, bj.w);
        float ww = fmaxf(rx - lx, 0.f), hh = fmaxf(ry - ly, 0.f);
        float inter = ww * hh;
        float iou = inter / (ai + aj - inter);
        if (j > i && j < PRE && iou > 0.7f) bits |= 1ULL << b;
    }
    g_mask[(size_t)i * NW + cb] = bits;
}

// ================================================================ pipelined serial NMS
// One warp. Removed-bitmap in registers (3 u64/lane). Two candidate groups
// ping-pong: while one group is decided, the other group's mask rows are in
// flight, hiding L2 latency. Queued candidates are re-checked against the
// live bitmap at decide time, in ascending index order == exact greedy NMS.

struct NmsCtx {
    u64 rem0, rem1, rem2;   // per-lane removed-bitmap words (lane, lane+32, lane+64)
    int cur;                // scan cursor: next index not yet queued (uniform)
    int nk;                 // keeps so far (uniform)
};

// find up to QD free indices >= ctx.cur, issue their row loads; returns count
__device__ __forceinline__ int nms_fill(NmsCtx& c, int lane,
                                        int* qj, u64* q0, u64* q1, u64* q2) {
    int cw = c.cur >> 6, cb = c.cur & 63;
    u64 m0 = ~c.rem0, m1 = ~c.rem1, m2 = ~c.rem2;
    if (lane < cw)            m0 = 0ULL; else if (lane == cw)      m0 &= (~0ULL) << cb;
    if (lane + 32 < cw)       m1 = 0ULL; else if (lane + 32 == cw) m1 &= (~0ULL) << cb;
    if (lane + 64 < cw)       m2 = 0ULL; else if (lane + 64 == cw) m2 &= (~0ULL) << cb;
    unsigned b0 = __ballot_sync(FULL, m0 != 0ULL);
    unsigned b1 = __ballot_sync(FULL, m1 != 0ULL);
    unsigned b2 = __ballot_sync(FULL, m2 != 0ULL);

    int cnt = 0;
    while (cnt < QD) {
        int wsel; u64 wfree;
        if (b0)      { int s = __ffs(b0) - 1; wsel = s;      wfree = __shfl_sync(FULL, m0, s); b0 &= b0 - 1; }
        else if (b1) { int s = __ffs(b1) - 1; wsel = s + 32; wfree = __shfl_sync(FULL, m1, s); b1 &= b1 - 1; }
        else if (b2) { int s = __ffs(b2) - 1; wsel = s + 64; wfree = __shfl_sync(FULL, m2, s); b2 &= b2 - 1; }
        else break;
        while (wfree && cnt < QD) {
            int b = __ffsll((long long)wfree) - 1;
            wfree &= wfree - 1;
            qj[cnt++] = (wsel << 6) + b;
        }
    }
    #pragma unroll
    for (int m = 0; m < QD; m++) if (m >= cnt) qj[m] = PRE;

    // issue row loads (triangular clamp: words below row start were never written)
    #pragma unroll
    for (int m = 0; m < QD; m++) {
        int jm = qj[m];
        if (jm < PRE) {
            int sw = jm >> 6;
            const u64* row = g_mask + (size_t)jm * NW;
            q0[m] = (lane      >= sw)                   ? row[lane]      : 0ULL;
            q1[m] = (lane + 32 >= sw)                   ? row[lane + 32] : 0ULL;
            q2[m] = (lane + 64 >= sw && lane + 64 < NW) ? row[lane + 64] : 0ULL;
        } else { q0[m] = 0ULL; q1[m] = 0ULL; q2[m] = 0ULL; }
    }
    if (cnt) c.cur = qj[cnt - 1] + 1;
    return cnt;
}

__device__ __forceinline__ void nms_decide(NmsCtx& c, int lane, int* s_keep,
                                           const int* qj, const u64* q0,
                                           const u64* q1, const u64* q2) {
    #pragma unroll
    for (int m = 0; m < QD; m++) {
        int jm = qj[m];
        if (jm >= PRE) break;
        int sw = jm >> 6;
        u64 bit = 1ULL << (jm & 63);
        bool supp = (lane == sw      && (c.rem0 & bit)) ||
                    (lane == sw - 32 && (c.rem1 & bit)) ||
                    (lane == sw - 64 && (c.rem2 & bit));
        if (__any_sync(FULL, supp)) continue;       // suppressed meanwhile
        if (lane == 0) s_keep[c.nk] = jm;
        c.nk++;
        c.rem0 |= q0[m]; c.rem1 |= q1[m]; c.rem2 |= q2[m];
        if (lane == (sw & 31)) {
            if (sw < 32)      c.rem0 |= bit;
            else if (sw < 64) c.rem1 |= bit;
            else              c.rem2 |= bit;
        }
        if (c.nk == POST) break;
    }
}

__global__ void k_nms(float* __restrict__ out) {
    __shared__ int s_keep[POST];
    int lane = threadIdx.x;        // 32 threads

    NmsCtx c;
    c.rem0 = 0ULL; c.rem1 = 0ULL; c.rem2 = 0ULL;
    if (lane == 29) c.rem2 = (~0ULL) << 48;   // word 93: indices 6000..6015 invalid
    if (lane >= 30) c.rem2 = ~0ULL;           // words 94,95 don't exist
    c.cur = 0; c.nk = 0;

    int ja[QD], jb[QD];
    u64 a0[QD], a1[QD], a2[QD], e0[QD], e1[QD], e2[QD];

    int ca = nms_fill(c, lane, ja, a0, a1, a2);
    int cb = nms_fill(c, lane, jb, e0, e1, e2);

    while (c.nk < POST && (ca | cb)) {
        nms_decide(c, lane, s_keep, ja, a0, a1, a2);
        if (c.nk >= POST) break;
        ca = nms_fill(c, lane, ja, a0, a1, a2);   // loads fly during decide of B
        nms_decide(c, lane, s_keep, jb, e0, e1, e2);
        if (c.nk >= POST) break;
        cb = nms_fill(c, lane, jb, e0, e1, e2);   // loads fly during decide of A
    }

    int nk = c.nk;
    __syncwarp();
    for (int k = nk + lane; k < POST; k += 32) s_keep[k] = 0;
    __syncwarp();
    for (int k = lane; k < POST; k += 32) {
        float4 b = g_top[s_keep[k]];
        out[k * 5 + 0] = 0.f;
        out[k * 5 + 1] = b.x;
        out[k * 5 + 2] = b.y;
        out[k * 5 + 3] = b.z;
        out[k * 5 + 4] = b.w;
    }
}

// ---------------------------------------------------------------- launch
extern "C" void kernel_launch(void* const* d_in, const int* in_sizes, int n_in,
                              void* d_out, int out_size) {
    const float* cls  = (const float*)d_in[0];
    const float* bbox = (const float*)d_in[1];
    const int*   ih   = (const int*)d_in[2];
    const int*   iw   = (const int*)d_in[3];
    float* out = (float*)d_out;

    k_decode <<<(NA + 255) / 256, 256>>>(cls, bbox, ih, iw);
    k_thresh <<<1, 1024>>>();
    k_compact<<<(NA + 255) / 256, 256>>>();
    k_rank2d <<<dim3(CAP / 256, CAP / 256), 256>>>();
    k_scatter<<<CAP / 256, 256>>>();
    k_mask   <<<dim3(NW, NW), 64>>>();
    k_nms    <<<1, 32>>>(out);
}